// round 11
// baseline (speedup 1.0000x reference)
#include <cuda_runtime.h>
#include <math.h>

// Problem constants
#define BB 2048
#define TT 26
#define II 1024
#define HH 512
#define G3 (3 * HH)   // 1536

// Scratch (device globals — no allocation allowed in kernel_launch)
__device__ float g_xg[(size_t)TT * BB * G3];   // [T][B][3H] input projections
__device__ float g_hg[(size_t)BB * G3];        // [B][3H] hidden projections (per step)
__device__ float g_h[(size_t)BB * HH];         // [B][H] current hidden state

// ---------------------------------------------------------------------------
// Tiled fp32 GEMM:  C[m,n] = sum_k A[m,k] * W[n,k] + bias[n]
// MODE 1: A = external (img), C = g_xg with [T][B][3H] remap (m = b*T + t)
// MODE 0: A = g_h,            C = g_hg row-major [B][3H]
// BM=BN=128, BK=8, 256 threads, 8x8 microtile.
// ---------------------------------------------------------------------------
#define BM 128
#define BN 128
#define BK 8
#define TM 8
#define TN 8

template <int MODE>
__global__ __launch_bounds__(256) void gemm_abt(const float* __restrict__ A_ext,
                                                const float* __restrict__ W,
                                                const float* __restrict__ bias,
                                                int M, int N, int K) {
    __shared__ float As[BK][BM];
    __shared__ float Bs[BK][BN];

    const float* __restrict__ A = (MODE == 0) ? (const float*)g_h : A_ext;

    const int tid = threadIdx.x;
    const int tx = tid & 15;        // 0..15  (N direction)
    const int ty = tid >> 4;        // 0..15  (M direction)
    const int bm = blockIdx.y * BM;
    const int bn = blockIdx.x * BN;

    // loader mapping: 256 threads, each loads one float4 of A-tile and one of W-tile
    const int lr = tid >> 1;        // row within tile (0..127)
    const int lc = (tid & 1) * 4;   // k-offset within BK (0 or 4)

    float acc[TM][TN];
#pragma unroll
    for (int i = 0; i < TM; i++)
#pragma unroll
        for (int j = 0; j < TN; j++) acc[i][j] = 0.0f;

    for (int k0 = 0; k0 < K; k0 += BK) {
        float4 av = *(const float4*)(A + (size_t)(bm + lr) * K + k0 + lc);
        As[lc + 0][lr] = av.x;
        As[lc + 1][lr] = av.y;
        As[lc + 2][lr] = av.z;
        As[lc + 3][lr] = av.w;
        float4 wv = *(const float4*)(W + (size_t)(bn + lr) * K + k0 + lc);
        Bs[lc + 0][lr] = wv.x;
        Bs[lc + 1][lr] = wv.y;
        Bs[lc + 2][lr] = wv.z;
        Bs[lc + 3][lr] = wv.w;
        __syncthreads();

#pragma unroll
        for (int k = 0; k < BK; k++) {
            float ra[TM], rb[TN];
            // vector LDS to cut bank conflicts
            float4 a0 = *(const float4*)&As[k][ty * TM];
            float4 a1 = *(const float4*)&As[k][ty * TM + 4];
            ra[0] = a0.x; ra[1] = a0.y; ra[2] = a0.z; ra[3] = a0.w;
            ra[4] = a1.x; ra[5] = a1.y; ra[6] = a1.z; ra[7] = a1.w;
            float4 b0 = *(const float4*)&Bs[k][tx * TN];
            float4 b1 = *(const float4*)&Bs[k][tx * TN + 4];
            rb[0] = b0.x; rb[1] = b0.y; rb[2] = b0.z; rb[3] = b0.w;
            rb[4] = b1.x; rb[5] = b1.y; rb[6] = b1.z; rb[7] = b1.w;
#pragma unroll
            for (int i = 0; i < TM; i++)
#pragma unroll
                for (int j = 0; j < TN; j++) acc[i][j] = fmaf(ra[i], rb[j], acc[i][j]);
        }
        __syncthreads();
    }

    // epilogue: add bias, store
    float bv[TN];
#pragma unroll
    for (int j = 0; j < TN; j++) bv[j] = bias[bn + tx * TN + j];

#pragma unroll
    for (int i = 0; i < TM; i++) {
        int m = bm + ty * TM + i;
        int ncol = bn + tx * TN;
        if (MODE == 1) {
            int b = m / TT;
            int t = m % TT;
            float* dst = g_xg + (size_t)t * BB * G3 + (size_t)b * G3 + ncol;
#pragma unroll
            for (int j = 0; j < TN; j++) dst[j] = acc[i][j] + bv[j];
        } else {
            float* dst = g_hg + (size_t)m * G3 + ncol;
#pragma unroll
            for (int j = 0; j < TN; j++) dst[j] = acc[i][j] + bv[j];
        }
    }
}

// ---------------------------------------------------------------------------
// GRU cell elementwise: reads g_xg[t], g_hg, g_h -> writes g_h and out[:,t,:]
// ---------------------------------------------------------------------------
__global__ void gru_cell(float* __restrict__ out, int t) {
    int idx = blockIdx.x * blockDim.x + threadIdx.x;
    if (idx >= BB * HH) return;
    int b = idx / HH;
    int j = idx - b * HH;

    const float* xg = g_xg + (size_t)t * BB * G3 + (size_t)b * G3;
    const float* hg = g_hg + (size_t)b * G3;

    float xr = xg[j], xz = xg[HH + j], xn = xg[2 * HH + j];
    float hr = hg[j], hz = hg[HH + j], hn = hg[2 * HH + j];

    float r = 1.0f / (1.0f + expf(-(xr + hr)));
    float z = 1.0f / (1.0f + expf(-(xz + hz)));
    float n = tanhf(xn + r * hn);
    float hprev = g_h[idx];
    float hnew = (1.0f - z) * n + z * hprev;

    g_h[idx] = hnew;
    out[(size_t)b * TT * HH + (size_t)t * HH + j] = hnew;
}

__global__ void zero_h() {
    int idx = blockIdx.x * blockDim.x + threadIdx.x;
    if (idx < BB * HH) g_h[idx] = 0.0f;
}

__global__ void copy_hidden(float* __restrict__ out_hidden) {
    int idx = blockIdx.x * blockDim.x + threadIdx.x;
    if (idx < BB * HH) out_hidden[idx] = g_h[idx];
}

// ---------------------------------------------------------------------------
// kernel_launch
// inputs: img_tensor [B,T,I], w_ih [3H,I], w_hh [3H,H], b_ih [3H], b_hh [3H]
// output: enc_outputs [B,T,H] then hidden [1,B,H] (concatenated)
// ---------------------------------------------------------------------------
extern "C" void kernel_launch(void* const* d_in, const int* in_sizes, int n_in,
                              void* d_out, int out_size) {
    const float* img  = (const float*)d_in[0];
    const float* w_ih = (const float*)d_in[1];
    const float* w_hh = (const float*)d_in[2];
    const float* b_ih = (const float*)d_in[3];
    const float* b_hh = (const float*)d_in[4];
    float* out = (float*)d_out;

    const int nBH = BB * HH;

    zero_h<<<(nBH + 255) / 256, 256>>>();

    // Precompute x_gates for all timesteps: M = B*T = 53248, N = 1536, K = 1024
    {
        dim3 grid(G3 / BN, (BB * TT) / BM);
        gemm_abt<1><<<grid, 256>>>(img, w_ih, b_ih, BB * TT, G3, II);
    }

    // Sequential recurrence
    for (int t = 0; t < TT; t++) {
        dim3 grid(G3 / BN, BB / BM);  // 12 x 16
        gemm_abt<0><<<grid, 256>>>(nullptr, w_hh, b_hh, BB, G3, HH);
        gru_cell<<<(nBH + 255) / 256, 256>>>(out, t);
    }

    // hidden state tail: out + B*T*H
    copy_hidden<<<(nBH + 255) / 256, 256>>>(out + (size_t)BB * TT * HH);
}

// round 12
// speedup vs baseline: 1.0022x; 1.0022x over previous
#include <cuda_runtime.h>
#include <math.h>

// Problem constants
#define BB 2048
#define TT 26
#define II 1024
#define HH 512
#define G3 (3 * HH)   // 1536

// Scratch (device globals — no allocation allowed in kernel_launch)
__device__ float g_xg[(size_t)TT * BB * G3];   // [T][B][3H] input projections
__device__ float g_hg[(size_t)BB * G3];        // [B][3H] hidden projections (per step)
__device__ float g_h[(size_t)BB * HH];         // [B][H] current hidden state

// ---------------------------------------------------------------------------
// Tiled fp32 GEMM:  C[m,n] = sum_k A[m,k] * W[n,k] + bias[n]
// MODE 1: A = external (img), C = g_xg with [T][B][3H] remap (m = b*T + t)
// MODE 0: A = g_h,            C = g_hg row-major [B][3H]
// BM=BN=128, BK=8, 256 threads, 8x8 microtile.
// ---------------------------------------------------------------------------
#define BM 128
#define BN 128
#define BK 8
#define TM 8
#define TN 8

template <int MODE>
__global__ __launch_bounds__(256) void gemm_abt(const float* __restrict__ A_ext,
                                                const float* __restrict__ W,
                                                const float* __restrict__ bias,
                                                int M, int N, int K) {
    __shared__ float As[BK][BM];
    __shared__ float Bs[BK][BN];

    const float* __restrict__ A = (MODE == 0) ? (const float*)g_h : A_ext;

    const int tid = threadIdx.x;
    const int tx = tid & 15;        // 0..15  (N direction)
    const int ty = tid >> 4;        // 0..15  (M direction)
    const int bm = blockIdx.y * BM;
    const int bn = blockIdx.x * BN;

    // loader mapping: 256 threads, each loads one float4 of A-tile and one of W-tile
    const int lr = tid >> 1;        // row within tile (0..127)
    const int lc = (tid & 1) * 4;   // k-offset within BK (0 or 4)

    float acc[TM][TN];
#pragma unroll
    for (int i = 0; i < TM; i++)
#pragma unroll
        for (int j = 0; j < TN; j++) acc[i][j] = 0.0f;

    for (int k0 = 0; k0 < K; k0 += BK) {
        float4 av = *(const float4*)(A + (size_t)(bm + lr) * K + k0 + lc);
        As[lc + 0][lr] = av.x;
        As[lc + 1][lr] = av.y;
        As[lc + 2][lr] = av.z;
        As[lc + 3][lr] = av.w;
        float4 wv = *(const float4*)(W + (size_t)(bn + lr) * K + k0 + lc);
        Bs[lc + 0][lr] = wv.x;
        Bs[lc + 1][lr] = wv.y;
        Bs[lc + 2][lr] = wv.z;
        Bs[lc + 3][lr] = wv.w;
        __syncthreads();

#pragma unroll
        for (int k = 0; k < BK; k++) {
            float ra[TM], rb[TN];
            // vector LDS to cut bank conflicts
            float4 a0 = *(const float4*)&As[k][ty * TM];
            float4 a1 = *(const float4*)&As[k][ty * TM + 4];
            ra[0] = a0.x; ra[1] = a0.y; ra[2] = a0.z; ra[3] = a0.w;
            ra[4] = a1.x; ra[5] = a1.y; ra[6] = a1.z; ra[7] = a1.w;
            float4 b0 = *(const float4*)&Bs[k][tx * TN];
            float4 b1 = *(const float4*)&Bs[k][tx * TN + 4];
            rb[0] = b0.x; rb[1] = b0.y; rb[2] = b0.z; rb[3] = b0.w;
            rb[4] = b1.x; rb[5] = b1.y; rb[6] = b1.z; rb[7] = b1.w;
#pragma unroll
            for (int i = 0; i < TM; i++)
#pragma unroll
                for (int j = 0; j < TN; j++) acc[i][j] = fmaf(ra[i], rb[j], acc[i][j]);
        }
        __syncthreads();
    }

    // epilogue: add bias, store
    float bv[TN];
#pragma unroll
    for (int j = 0; j < TN; j++) bv[j] = bias[bn + tx * TN + j];

#pragma unroll
    for (int i = 0; i < TM; i++) {
        int m = bm + ty * TM + i;
        int ncol = bn + tx * TN;
        if (MODE == 1) {
            int b = m / TT;
            int t = m % TT;
            float* dst = g_xg + (size_t)t * BB * G3 + (size_t)b * G3 + ncol;
#pragma unroll
            for (int j = 0; j < TN; j++) dst[j] = acc[i][j] + bv[j];
        } else {
            float* dst = g_hg + (size_t)m * G3 + ncol;
#pragma unroll
            for (int j = 0; j < TN; j++) dst[j] = acc[i][j] + bv[j];
        }
    }
}

// ---------------------------------------------------------------------------
// GRU cell elementwise: reads g_xg[t], g_hg, g_h -> writes g_h and out[:,t,:]
// ---------------------------------------------------------------------------
__global__ void gru_cell(float* __restrict__ out, int t) {
    int idx = blockIdx.x * blockDim.x + threadIdx.x;
    if (idx >= BB * HH) return;
    int b = idx / HH;
    int j = idx - b * HH;

    const float* xg = g_xg + (size_t)t * BB * G3 + (size_t)b * G3;
    const float* hg = g_hg + (size_t)b * G3;

    float xr = xg[j], xz = xg[HH + j], xn = xg[2 * HH + j];
    float hr = hg[j], hz = hg[HH + j], hn = hg[2 * HH + j];

    float r = 1.0f / (1.0f + expf(-(xr + hr)));
    float z = 1.0f / (1.0f + expf(-(xz + hz)));
    float n = tanhf(xn + r * hn);
    float hprev = g_h[idx];
    float hnew = (1.0f - z) * n + z * hprev;

    g_h[idx] = hnew;
    out[(size_t)b * TT * HH + (size_t)t * HH + j] = hnew;
}

__global__ void zero_h() {
    int idx = blockIdx.x * blockDim.x + threadIdx.x;
    if (idx < BB * HH) g_h[idx] = 0.0f;
}

__global__ void copy_hidden(float* __restrict__ out_hidden) {
    int idx = blockIdx.x * blockDim.x + threadIdx.x;
    if (idx < BB * HH) out_hidden[idx] = g_h[idx];
}

// ---------------------------------------------------------------------------
// kernel_launch
// inputs: img_tensor [B,T,I], w_ih [3H,I], w_hh [3H,H], b_ih [3H], b_hh [3H]
// output: enc_outputs [B,T,H] then hidden [1,B,H] (concatenated)
// ---------------------------------------------------------------------------
extern "C" void kernel_launch(void* const* d_in, const int* in_sizes, int n_in,
                              void* d_out, int out_size) {
    const float* img  = (const float*)d_in[0];
    const float* w_ih = (const float*)d_in[1];
    const float* w_hh = (const float*)d_in[2];
    const float* b_ih = (const float*)d_in[3];
    const float* b_hh = (const float*)d_in[4];
    float* out = (float*)d_out;

    const int nBH = BB * HH;

    zero_h<<<(nBH + 255) / 256, 256>>>();

    // Precompute x_gates for all timesteps: M = B*T = 53248, N = 1536, K = 1024
    {
        dim3 grid(G3 / BN, (BB * TT) / BM);
        gemm_abt<1><<<grid, 256>>>(img, w_ih, b_ih, BB * TT, G3, II);
    }

    // Sequential recurrence
    for (int t = 0; t < TT; t++) {
        dim3 grid(G3 / BN, BB / BM);  // 12 x 16
        gemm_abt<0><<<grid, 256>>>(nullptr, w_hh, b_hh, BB, G3, HH);
        gru_cell<<<(nBH + 255) / 256, 256>>>(out, t);
    }

    // hidden state tail: out + B*T*H
    copy_hidden<<<(nBH + 255) / 256, 256>>>(out + (size_t)BB * TT * HH);
}